// round 4
// baseline (speedup 1.0000x reference)
#include <cuda_runtime.h>
#include <math.h>
#include <stdint.h>

// Problem constants
#define Tt   512
#define Bb   64
#define Dd   256
#define Uu   512
#define Mm   64
#define NZt  2112   // 4*U + M

#define NUBLK 128   // u-blocks: 4 u-cols each (16 z-cols)
#define NEBLK 16    // e-blocks: 4 e-cols each
#define NBLK  144
#define NTHR  256

// ---------------- device scratch ----------------
__device__ float g_Z[(size_t)Tt * NZt * Bb];   // Z[t][n][b] = x_t@Wcat + bcat
__device__ float g_h2[2][Uu][Bb];              // hidden state, TRANSPOSED [u][b], double buffered
__device__ float g_ze[Bb][Mm];                 // pre-softmax e logits
__device__ float g_eprob[Bb][Mm];              // normalized softmax probs
__device__ unsigned int g_bar4[4];             // striped grid barrier counters
__device__ unsigned int g_eflag;               // e logits ready
__device__ unsigned int g_eflag2;              // e probs ready

// SMEM float offsets
#define OFF_US   0              // u: [512*16], e: [512*4]
#define OFF_CR   8192           // cring [64 slot][4 u][64 b] = 16384
#define OFF_HS0  24576          // h chunk buf0 [64*65] = 4160
#define OFF_HS1  28736          // h chunk buf1
#define OFF_ZT   32896          // zt [16 c][65] = 1040
#define OFF_ZES  33936          // zes [64 b][65] = 4160
#define SMEM_F   38096          // 152384 bytes

// ---------------- init ----------------
__global__ void init_kernel() {
    int tid = blockIdx.x * blockDim.x + threadIdx.x;
    float* h0 = &g_h2[0][0][0];
    for (int i = tid; i < Uu * Bb; i += gridDim.x * blockDim.x) h0[i] = 0.0f;
    if (tid < 4) g_bar4[tid] = 0u;
    if (tid == 4) g_eflag = 0u;
    if (tid == 5) g_eflag2 = 0u;
}

// ---------------- precompute: Z[t][n][b] = bcat[n] + sum_k x[b][t][k]*Wcat[k][n] ----------------
__global__ __launch_bounds__(256) void precompute_kernel(
    const float* __restrict__ x,
    const float* __restrict__ Wi, const float* __restrict__ Wf,
    const float* __restrict__ Wo, const float* __restrict__ Wc,
    const float* __restrict__ We,
    const float* __restrict__ bi, const float* __restrict__ bf,
    const float* __restrict__ bo, const float* __restrict__ bc,
    const float* __restrict__ be)
{
    __shared__ float xs[64 * 65];
    __shared__ float Ws[64 * 64];

    const int nt  = blockIdx.x;     // 0..32  (0..31: gates, 32: e)
    const int t   = blockIdx.y;
    const int tid = threadIdx.x;

    const float* W; const float* bv;
    switch (nt >> 3) {
        case 0:  W = Wi; bv = bi; break;
        case 1:  W = Wf; bv = bf; break;
        case 2:  W = Wo; bv = bo; break;
        case 3:  W = Wc; bv = bc; break;
        default: W = We; bv = be; break;
    }
    const int stride = (nt < 32) ? Uu : Mm;
    const int col0   = (nt & 7) * 64;

    const int tx = tid & 15, ty = tid >> 4;

    float acc[4][4];
    #pragma unroll
    for (int j = 0; j < 4; j++) {
        float b0 = bv[col0 + tx * 4 + j];
        #pragma unroll
        for (int i = 0; i < 4; i++) acc[i][j] = b0;
    }

    for (int kb = 0; kb < 4; kb++) {
        __syncthreads();
        #pragma unroll
        for (int l = 0; l < 16; l++) {
            int idx = l * 256 + tid;
            int b = idx >> 6, kk = idx & 63;
            xs[b * 65 + kk] = x[(size_t)b * Tt * Dd + (size_t)t * Dd + kb * 64 + kk];
        }
        #pragma unroll
        for (int l = 0; l < 16; l++) {
            int idx = l * 256 + tid;
            int kk = idx >> 6, nn = idx & 63;
            Ws[kk * 64 + nn] = W[(size_t)(kb * 64 + kk) * stride + col0 + nn];
        }
        __syncthreads();
        #pragma unroll 16
        for (int kk = 0; kk < 64; kk++) {
            float4 wv = *reinterpret_cast<const float4*>(&Ws[kk * 64 + tx * 4]);
            #pragma unroll
            for (int i = 0; i < 4; i++) {
                float xv = xs[(ty * 4 + i) * 65 + kk];
                acc[i][0] += xv * wv.x;
                acc[i][1] += xv * wv.y;
                acc[i][2] += xv * wv.z;
                acc[i][3] += xv * wv.w;
            }
        }
    }

    #pragma unroll
    for (int j = 0; j < 4; j++) {
        int n = nt * 64 + tx * 4 + j;
        float4 v = make_float4(acc[0][j], acc[1][j], acc[2][j], acc[3][j]);
        *reinterpret_cast<float4*>(&g_Z[((size_t)t * NZt + n) * Bb + ty * 4]) = v;
    }
}

// ---------------- persistent recurrent kernel ----------------
__global__ __launch_bounds__(NTHR, 1) void recur_kernel(
    float* __restrict__ out,
    const float* __restrict__ Ui, const float* __restrict__ Uf,
    const float* __restrict__ Uo, const float* __restrict__ Uc,
    const float* __restrict__ Ue)
{
    extern __shared__ float sm[];
    float* Us  = sm + OFF_US;
    float* cr  = sm + OFF_CR;
    float* hsA = sm + OFF_HS0;
    float* hsB = sm + OFF_HS1;
    float* zt  = sm + OFF_ZT;
    float* zes = sm + OFF_ZES;

    const int bid = blockIdx.x;
    const int tid = threadIdx.x;
    const bool isE = (bid >= NUBLK);

    // --- load persistent U slice (once) ---
    if (!isE) {
        const int u0 = bid * 4;
        const int tc = tid & 15;                 // column c = gate*4 + uul
        const float* Ug;
        switch (tc >> 2) {
            case 0:  Ug = Ui; break;
            case 1:  Ug = Uf; break;
            case 2:  Ug = Uo; break;
            default: Ug = Uc; break;
        }
        const int lc = u0 + (tc & 3);
        for (int k = tid >> 4; k < Uu; k += NTHR / 16)
            Us[k * 16 + tc] = Ug[(size_t)k * Uu + lc];
    } else {
        const int m0 = (bid - NUBLK) * 4;
        const int tc = tid & 3;
        for (int k = tid >> 2; k < Uu; k += NTHR / 4)
            Us[k * 4 + tc] = Ue[(size_t)k * Mm + m0 + tc];
    }
    __syncthreads();

    // u-block GEMM map: tx = gate (0..3), ty = batch row (0..63)
    const int tx = tid & 3, ty = tid >> 2;

    for (int t = 0; t < Tt; t++) {
        const float* hsrc = &g_h2[t & 1][0][0];   // [512 k][64 b]

        if (!isE) {
            const int u0 = bid * 4;

            // Z prefetch (gate tx, u-cols u0..u0+3, batch row ty)
            float acc0, acc1, acc2, acc3;
            {
                const float* zp = &g_Z[((size_t)t * NZt + tx * Uu + u0) * Bb + ty];
                acc0 = zp[0];
                acc1 = zp[64];
                acc2 = zp[128];
                acc3 = zp[192];
            }
            // fill h chunk 0
            {
                float pf[16];
                #pragma unroll
                for (int l = 0; l < 16; l++) pf[l] = hsrc[l * 256 + tid];
                #pragma unroll
                for (int l = 0; l < 16; l++) {
                    int idx = l * 256 + tid;
                    hsA[(idx & 63) * 65 + (idx >> 6)] = pf[l];
                }
            }
            __syncthreads();

            // ---- GEMM: z += h @ U_slice, double-buffered ----
            for (int kb = 0; kb < 8; kb++) {
                float* hc = (kb & 1) ? hsB : hsA;
                float* hn = (kb & 1) ? hsA : hsB;
                float pf[16];
                if (kb < 7) {
                    const float* s = hsrc + (kb + 1) * 4096;
                    #pragma unroll
                    for (int l = 0; l < 16; l++) pf[l] = s[l * 256 + tid];
                }
                const float* Ub = &Us[kb * 64 * 16 + tx * 4];
                const float* hp = &hc[ty * 65];
                #pragma unroll 16
                for (int kk = 0; kk < 64; kk++) {
                    float4 uv = *reinterpret_cast<const float4*>(&Ub[kk * 16]);
                    float hv = hp[kk];
                    acc0 += hv * uv.x;
                    acc1 += hv * uv.y;
                    acc2 += hv * uv.z;
                    acc3 += hv * uv.w;
                }
                if (kb < 7) {
                    #pragma unroll
                    for (int l = 0; l < 16; l++) {
                        int idx = l * 256 + tid;
                        hn[(idx & 63) * 65 + (idx >> 6)] = pf[l];
                    }
                }
                __syncthreads();
            }
            // epilogue: zt[c][r], c = tx*4 + j
            zt[(tx * 4 + 0) * 65 + ty] = acc0;
            zt[(tx * 4 + 1) * 65 + ty] = acc1;
            zt[(tx * 4 + 2) * 65 + ty] = acc2;
            zt[(tx * 4 + 3) * 65 + ty] = acc3;

            // ---- wait for softmax probs (computed by e-block 0 in parallel) ----
            if (tid == 0) {
                while (*(volatile unsigned int*)&g_eflag2 < (unsigned)(t + 1)) { }
                __threadfence();   // acquire: invalidate L1
            }
            __syncthreads();

            // load probs to SMEM
            #pragma unroll
            for (int l = 0; l < 16; l++) {
                int idx = l * 256 + tid;          // b = idx>>6, m = idx&63
                zes[(idx >> 6) * 65 + (idx & 63)] = (&g_eprob[0][0])[idx];
            }
            __syncthreads();

            // ---- phase 2: memory read + update (uul = tid>>6, b = tid&63) ----
            {
                const int uul = tid >> 6, b = tid & 63;
                const int mlim = (t < 64) ? t : 64;
                float p0 = 0.f, p1 = 0.f, p2 = 0.f, p3 = 0.f;
                const float* zr = &zes[b * 65];
                int m = 0;
                for (; m + 4 <= mlim; m += 4) {
                    int s0 = (t - 1 - m) & 63, s1 = (t - 2 - m) & 63;
                    int s2 = (t - 3 - m) & 63, s3 = (t - 4 - m) & 63;
                    p0 += zr[m]     * cr[(s0 * 4 + uul) * 64 + b];
                    p1 += zr[m + 1] * cr[(s1 * 4 + uul) * 64 + b];
                    p2 += zr[m + 2] * cr[(s2 * 4 + uul) * 64 + b];
                    p3 += zr[m + 3] * cr[(s3 * 4 + uul) * 64 + b];
                }
                for (; m < mlim; m++)
                    p0 += zr[m] * cr[(((t - 1 - m) & 63) * 4 + uul) * 64 + b];
                float mc = (p0 + p1) + (p2 + p3);

                float iv = zt[(uul)      * 65 + b];
                float fv = zt[(4 + uul)  * 65 + b];
                float ov = zt[(8 + uul)  * 65 + b];
                float cv = zt[(12 + uul) * 65 + b];
                iv = 1.0f / (1.0f + __expf(-iv));
                fv = 1.0f / (1.0f + __expf(-fv));
                ov = 1.0f / (1.0f + __expf(-ov));
                cv = tanhf(cv);
                float c = fv * mc + iv * cv;
                float h = ov * tanhf(c);
                cr[((t & 63) * 4 + uul) * 64 + b] = c;             // block-private ring
                g_h2[(t + 1) & 1][u0 + uul][b] = h;                // coalesced
                out[((size_t)b * Tt + t) * Uu + u0 + uul] = h;
            }
        } else {
            // ---- e-block: small GEMM producing ze ----
            const int m0 = (bid - NUBLK) * 4;
            const int eb = tid >> 2, em = tid & 3;
            float a0 = 0.f, a1 = 0.f;

            // fill h chunk 0
            {
                float pf[16];
                #pragma unroll
                for (int l = 0; l < 16; l++) pf[l] = hsrc[l * 256 + tid];
                #pragma unroll
                for (int l = 0; l < 16; l++) {
                    int idx = l * 256 + tid;
                    hsA[(idx & 63) * 65 + (idx >> 6)] = pf[l];
                }
            }
            __syncthreads();

            for (int kb = 0; kb < 8; kb++) {
                float* hc = (kb & 1) ? hsB : hsA;
                float* hn = (kb & 1) ? hsA : hsB;
                float pf[16];
                if (kb < 7) {
                    const float* s = hsrc + (kb + 1) * 4096;
                    #pragma unroll
                    for (int l = 0; l < 16; l++) pf[l] = s[l * 256 + tid];
                }
                const float* hp = &hc[eb * 65];
                const float* Up = &Us[kb * 64 * 4 + em];
                #pragma unroll 16
                for (int kk = 0; kk < 64; kk += 2) {
                    a0 += hp[kk]     * Up[kk * 4];
                    a1 += hp[kk + 1] * Up[(kk + 1) * 4];
                }
                if (kb < 7) {
                    #pragma unroll
                    for (int l = 0; l < 16; l++) {
                        int idx = l * 256 + tid;
                        hn[(idx & 63) * 65 + (idx >> 6)] = pf[l];
                    }
                }
                __syncthreads();
            }
            float acc = a0 + a1
                      + g_Z[((size_t)t * NZt + 4 * Uu + m0 + em) * Bb + eb];
            g_ze[eb][m0 + em] = acc;
            __threadfence();
            __syncthreads();
            if (tid == 0) atomicAdd(&g_eflag, 1u);

            // e-block 0 additionally normalizes the softmax
            if (bid == NUBLK) {
                if (tid == 0) {
                    unsigned tgt = (unsigned)(t + 1) * (unsigned)NEBLK;
                    while (*(volatile unsigned int*)&g_eflag < tgt) { }
                    __threadfence();
                }
                __syncthreads();
                if (tid < 64) {
                    const int b = tid;
                    float mx = -1e30f;
                    #pragma unroll 8
                    for (int m = 0; m < 64; m++) mx = fmaxf(mx, g_ze[b][m]);
                    float s = 0.0f;
                    #pragma unroll 8
                    for (int m = 0; m < 64; m++) s += __expf(g_ze[b][m] - mx);
                    float inv = 1.0f / s;
                    #pragma unroll 8
                    for (int m = 0; m < 64; m++)
                        g_eprob[b][m] = __expf(g_ze[b][m] - mx) * inv;
                    __threadfence();
                }
                __syncthreads();
                if (tid == 0) atomicAdd(&g_eflag2, 1u);
            }
        }

        // ---- grid barrier (striped counters, monotonic targets) ----
        __syncthreads();
        if (tid == 0) { __threadfence(); atomicAdd(&g_bar4[bid & 3], 1u); }
        if (tid < 4) {
            unsigned tgt = (unsigned)(t + 1) * (unsigned)(NBLK / 4);
            while (*(volatile unsigned int*)&g_bar4[tid] < tgt) { }
            __threadfence();            // acquire: invalidate L1 before reading new h
        }
        __syncthreads();
    }
}

// ---------------- launch ----------------
extern "C" void kernel_launch(void* const* d_in, const int* in_sizes, int n_in,
                              void* d_out, int out_size) {
    (void)in_sizes; (void)n_in; (void)out_size;
    const float* x  = (const float*)d_in[0];
    const float* Wi = (const float*)d_in[1];
    const float* Ui = (const float*)d_in[2];
    const float* bi = (const float*)d_in[3];
    const float* Wf = (const float*)d_in[4];
    const float* Uf = (const float*)d_in[5];
    const float* bf = (const float*)d_in[6];
    const float* Wo = (const float*)d_in[7];
    const float* Uo = (const float*)d_in[8];
    const float* bo = (const float*)d_in[9];
    const float* Wc = (const float*)d_in[10];
    const float* Uc = (const float*)d_in[11];
    const float* bc = (const float*)d_in[12];
    const float* We = (const float*)d_in[13];
    const float* Ue = (const float*)d_in[14];
    const float* be = (const float*)d_in[15];
    float* out = (float*)d_out;

    const size_t SMEM = (size_t)SMEM_F * sizeof(float);   // 152384 B
    cudaFuncSetAttribute(recur_kernel, cudaFuncAttributeMaxDynamicSharedMemorySize, (int)SMEM);

    init_kernel<<<32, 256>>>();
    dim3 pg(33, Tt);
    precompute_kernel<<<pg, 256>>>(x, Wi, Wf, Wo, Wc, We, bi, bf, bo, bc, be);
    recur_kernel<<<NBLK, NTHR, SMEM>>>(out, Ui, Uf, Uo, Uc, Ue);
}

// round 6
// speedup vs baseline: 1.3714x; 1.3714x over previous
#include <cuda_runtime.h>
#include <math.h>
#include <stdint.h>

// Problem constants
#define Tt   512
#define Bb   64
#define Dd   256
#define Uu   512
#define Mm   64
#define NZt  2112   // 4*U + M

#define NUBLK 128   // u-blocks: 4 u-cols each (16 z-cols)
#define NEBLK 16    // e-blocks: 4 e-cols each
#define NBLK  144
#define NTHR  256

// ---------------- device scratch ----------------
__device__ float g_Z[(size_t)Tt * NZt * Bb];   // Z[t][n][b] = x_t@Wcat + bcat
__device__ float g_hT[2][Bb][Uu];              // hidden state [b][u], double buffered
__device__ float g_ze[Bb][Mm];                 // pre-softmax e logits
__device__ unsigned int g_bar4[4];             // striped grid barrier counters
__device__ unsigned int g_eflag;               // e logits ready counter

// SMEM float offsets
#define OFF_US   0              // u: [8][64k][16c] ; e: [512k][4c]
#define OFF_CR   8192           // cring [64 slot][4 u][64 b] = 16384
#define OFF_HS0  24576          // h chunk buf0 [64 b][68] = 4352
#define OFF_HS1  28928          // h chunk buf1
#define OFF_ZT   33280          // zt [16 c][65] = 1040
#define OFF_ZES  34320          // zes [64 b][65] = 4160
#define SMEM_F   38480          // 153920 bytes

// ---------------- cp.async helpers ----------------
__device__ __forceinline__ void cp16(uint32_t dst, const float* src) {
    asm volatile("cp.async.ca.shared.global [%0], [%1], 16;" :: "r"(dst), "l"(src));
}
__device__ __forceinline__ void cp_commit() {
    asm volatile("cp.async.commit_group;");
}
__device__ __forceinline__ void cp_wait0() {
    asm volatile("cp.async.wait_group 0;");
}

// ---------------- init ----------------
__global__ void init_kernel() {
    int tid = blockIdx.x * blockDim.x + threadIdx.x;
    float* h0 = &g_hT[0][0][0];
    for (int i = tid; i < 2 * Bb * Uu; i += gridDim.x * blockDim.x) h0[i] = 0.0f;
    if (tid < 4) g_bar4[tid] = 0u;
    if (tid == 4) g_eflag = 0u;
}

// ---------------- precompute: Z[t][n][b] = bcat[n] + sum_k x[b][t][k]*Wcat[k][n] ----------------
__global__ __launch_bounds__(256) void precompute_kernel(
    const float* __restrict__ x,
    const float* __restrict__ Wi, const float* __restrict__ Wf,
    const float* __restrict__ Wo, const float* __restrict__ Wc,
    const float* __restrict__ We,
    const float* __restrict__ bi, const float* __restrict__ bf,
    const float* __restrict__ bo, const float* __restrict__ bc,
    const float* __restrict__ be)
{
    __shared__ float xs[64 * 65];
    __shared__ float Ws[64 * 64];

    const int nt  = blockIdx.x;     // 0..32  (0..31: gates, 32: e)
    const int t   = blockIdx.y;
    const int tid = threadIdx.x;

    const float* W; const float* bv;
    switch (nt >> 3) {
        case 0:  W = Wi; bv = bi; break;
        case 1:  W = Wf; bv = bf; break;
        case 2:  W = Wo; bv = bo; break;
        case 3:  W = Wc; bv = bc; break;
        default: W = We; bv = be; break;
    }
    const int stride = (nt < 32) ? Uu : Mm;
    const int col0   = (nt & 7) * 64;

    const int tx = tid & 15, ty = tid >> 4;

    float acc[4][4];
    #pragma unroll
    for (int j = 0; j < 4; j++) {
        float b0 = bv[col0 + tx * 4 + j];
        #pragma unroll
        for (int i = 0; i < 4; i++) acc[i][j] = b0;
    }

    for (int kb = 0; kb < 4; kb++) {
        __syncthreads();
        #pragma unroll
        for (int l = 0; l < 16; l++) {
            int idx = l * 256 + tid;
            int b = idx >> 6, kk = idx & 63;
            xs[b * 65 + kk] = x[(size_t)b * Tt * Dd + (size_t)t * Dd + kb * 64 + kk];
        }
        #pragma unroll
        for (int l = 0; l < 16; l++) {
            int idx = l * 256 + tid;
            int kk = idx >> 6, nn = idx & 63;
            Ws[kk * 64 + nn] = W[(size_t)(kb * 64 + kk) * stride + col0 + nn];
        }
        __syncthreads();
        #pragma unroll 16
        for (int kk = 0; kk < 64; kk++) {
            float4 wv = *reinterpret_cast<const float4*>(&Ws[kk * 64 + tx * 4]);
            #pragma unroll
            for (int i = 0; i < 4; i++) {
                float xv = xs[(ty * 4 + i) * 65 + kk];
                acc[i][0] += xv * wv.x;
                acc[i][1] += xv * wv.y;
                acc[i][2] += xv * wv.z;
                acc[i][3] += xv * wv.w;
            }
        }
    }

    #pragma unroll
    for (int j = 0; j < 4; j++) {
        int n = nt * 64 + tx * 4 + j;
        float4 v = make_float4(acc[0][j], acc[1][j], acc[2][j], acc[3][j]);
        *reinterpret_cast<float4*>(&g_Z[((size_t)t * NZt + n) * Bb + ty * 4]) = v;
    }
}

// ---------------- persistent recurrent kernel ----------------
__global__ __launch_bounds__(NTHR, 1) void recur_kernel(
    float* __restrict__ out,
    const float* __restrict__ Ui, const float* __restrict__ Uf,
    const float* __restrict__ Uo, const float* __restrict__ Uc,
    const float* __restrict__ Ue)
{
    extern __shared__ float sm[];
    float* Us  = sm + OFF_US;
    float* cr  = sm + OFF_CR;
    float* hsA = sm + OFF_HS0;
    float* hsB = sm + OFF_HS1;
    float* zt  = sm + OFF_ZT;
    float* zes = sm + OFF_ZES;

    const uint32_t smem_u = (uint32_t)__cvta_generic_to_shared(sm);
    const uint32_t hsAu = smem_u + OFF_HS0 * 4;
    const uint32_t hsBu = smem_u + OFF_HS1 * 4;

    const int bid = blockIdx.x;
    const int tid = threadIdx.x;
    const bool isE = (bid >= NUBLK);

    // --- load persistent U slice (once) ---
    if (!isE) {
        const int u0 = bid * 4;
        const int tc = tid & 15;                 // column c = gate*4 + uul
        const float* Ug;
        switch (tc >> 2) {
            case 0:  Ug = Ui; break;
            case 1:  Ug = Uf; break;
            case 2:  Ug = Uo; break;
            default: Ug = Uc; break;
        }
        const int lc = u0 + (tc & 3);
        for (int k = tid >> 4; k < Uu; k += NTHR / 16)
            Us[k * 16 + tc] = Ug[(size_t)k * Uu + lc];
    } else {
        const int m0 = (bid - NUBLK) * 4;
        const int tc = tid & 3;
        for (int k = tid >> 2; k < Uu; k += NTHR / 4)
            Us[k * 4 + tc] = Ue[(size_t)k * Mm + m0 + tc];
    }
    __syncthreads();

    // GEMM maps
    const int tx = tid & 3, ty = tid >> 2;        // u-blocks: col group / batch row
    const int fb = tid >> 2, fs = tid & 3;        // fill map: row b, 64B segment

    for (int t = 0; t < Tt; t++) {
        const float* hsrc = &g_hT[t & 1][0][0];   // [64 b][512 u]
        const float* fsrc = hsrc + (size_t)fb * Uu + fs * 16;

        if (!isE) {
            const int u0 = bid * 4;

            // Z loads for epilogue (independent, hidden behind GEMM)
            float zl0, zl1, zl2, zl3;
            {
                const float* zp = &g_Z[((size_t)t * NZt + tx * Uu + u0) * Bb + ty];
                zl0 = zp[0];
                zl1 = zp[64];
                zl2 = zp[128];
                zl3 = zp[192];
            }

            // prologue: fill chunk 0 (async)
            {
                uint32_t d = hsAu + (uint32_t)(fb * 68 + fs * 16) * 4;
                #pragma unroll
                for (int j = 0; j < 4; j++) cp16(d + j * 16, fsrc + j * 4);
                cp_commit();
            }

            float acc0 = 0.f, acc1 = 0.f, acc2 = 0.f, acc3 = 0.f;

            // ---- GEMM: z = h @ U_slice, cp.async double-buffered ----
            for (int kb = 0; kb < 8; kb++) {
                cp_wait0();
                __syncthreads();
                if (kb < 7) {
                    uint32_t d = ((kb & 1) ? hsAu : hsBu) + (uint32_t)(fb * 68 + fs * 16) * 4;
                    const float* s = fsrc + (kb + 1) * 64;
                    #pragma unroll
                    for (int j = 0; j < 4; j++) cp16(d + j * 16, s + j * 4);
                    cp_commit();
                }
                const float* hp = ((kb & 1) ? hsB : hsA) + ty * 68;
                const float* Ub = &Us[kb * 1024 + tx * 4];
                #pragma unroll
                for (int kk = 0; kk < 64; kk += 2) {
                    float2 hv = *reinterpret_cast<const float2*>(&hp[kk]);
                    float4 u0v = *reinterpret_cast<const float4*>(&Ub[kk * 16]);
                    float4 u1v = *reinterpret_cast<const float4*>(&Ub[kk * 16 + 16]);
                    acc0 += hv.x * u0v.x;
                    acc1 += hv.x * u0v.y;
                    acc2 += hv.x * u0v.z;
                    acc3 += hv.x * u0v.w;
                    acc0 += hv.y * u1v.x;
                    acc1 += hv.y * u1v.y;
                    acc2 += hv.y * u1v.z;
                    acc3 += hv.y * u1v.w;
                }
                __syncthreads();
            }
            // epilogue: add Z, stash in zt[c][b]
            zt[(tx * 4 + 0) * 65 + ty] = acc0 + zl0;
            zt[(tx * 4 + 1) * 65 + ty] = acc1 + zl1;
            zt[(tx * 4 + 2) * 65 + ty] = acc2 + zl2;
            zt[(tx * 4 + 3) * 65 + ty] = acc3 + zl3;

            // ---- wait for e logits (e-blocks finished long ago) ----
            if (tid == 0) {
                unsigned tgt = (unsigned)(t + 1) * (unsigned)NEBLK;
                while (*(volatile unsigned int*)&g_eflag < tgt) { }
                __threadfence();   // acquire: invalidate L1
            }
            __syncthreads();

            // coalesced load of ze logits into SMEM
            #pragma unroll
            for (int l = 0; l < 4; l++) {
                int i4 = l * 256 + tid;                       // float4 index
                float4 v = reinterpret_cast<const float4*>(&g_ze[0][0])[i4];
                int b = i4 >> 4, m = (i4 & 15) * 4;
                zes[b * 65 + m]     = v.x;
                zes[b * 65 + m + 1] = v.y;
                zes[b * 65 + m + 2] = v.z;
                zes[b * 65 + m + 3] = v.w;
            }
            __syncthreads();

            // ---- local softmax: 4 lanes per batch row, shfl reduce ----
            {
                const int b = tid >> 2, q = tid & 3;
                float v[16];
                float mx = -1e30f;
                #pragma unroll
                for (int i = 0; i < 16; i++) {
                    v[i] = zes[b * 65 + q * 16 + i];
                    mx = fmaxf(mx, v[i]);
                }
                mx = fmaxf(mx, __shfl_xor_sync(0xffffffffu, mx, 1));
                mx = fmaxf(mx, __shfl_xor_sync(0xffffffffu, mx, 2));
                float s = 0.f;
                #pragma unroll
                for (int i = 0; i < 16; i++) { v[i] = __expf(v[i] - mx); s += v[i]; }
                s += __shfl_xor_sync(0xffffffffu, s, 1);
                s += __shfl_xor_sync(0xffffffffu, s, 2);
                float inv = 1.0f / s;
                #pragma unroll
                for (int i = 0; i < 16; i++) zes[b * 65 + q * 16 + i] = v[i] * inv;
            }
            __syncthreads();

            // ---- phase 2: memory read + update (uul = tid>>6, b = tid&63) ----
            {
                const int uul = tid >> 6, b = tid & 63;
                const int mlim = (t < 64) ? t : 64;
                float p0 = 0.f, p1 = 0.f, p2 = 0.f, p3 = 0.f;
                const float* zr = &zes[b * 65];
                int m = 0;
                for (; m + 4 <= mlim; m += 4) {
                    int s0 = (t - 1 - m) & 63, s1 = (t - 2 - m) & 63;
                    int s2 = (t - 3 - m) & 63, s3 = (t - 4 - m) & 63;
                    p0 += zr[m]     * cr[(s0 * 4 + uul) * 64 + b];
                    p1 += zr[m + 1] * cr[(s1 * 4 + uul) * 64 + b];
                    p2 += zr[m + 2] * cr[(s2 * 4 + uul) * 64 + b];
                    p3 += zr[m + 3] * cr[(s3 * 4 + uul) * 64 + b];
                }
                for (; m < mlim; m++)
                    p0 += zr[m] * cr[(((t - 1 - m) & 63) * 4 + uul) * 64 + b];
                float mc = (p0 + p1) + (p2 + p3);

                float iv = zt[(uul)      * 65 + b];
                float fv = zt[(4 + uul)  * 65 + b];
                float ov = zt[(8 + uul)  * 65 + b];
                float cv = zt[(12 + uul) * 65 + b];
                iv = 1.0f / (1.0f + __expf(-iv));
                fv = 1.0f / (1.0f + __expf(-fv));
                ov = 1.0f / (1.0f + __expf(-ov));
                cv = tanhf(cv);
                float c = fv * mc + iv * cv;
                float h = ov * tanhf(c);
                cr[((t & 63) * 4 + uul) * 64 + b] = c;             // block-private ring
                g_hT[(t + 1) & 1][b][u0 + uul] = h;
                out[((size_t)b * Tt + t) * Uu + u0 + uul] = h;
            }
        } else {
            // ---- e-block: small GEMM producing ze ----
            const int m0 = (bid - NUBLK) * 4;
            const int eb = tid >> 2, em = tid & 3;
            float a0 = 0.f, a1 = 0.f;

            {
                uint32_t d = hsAu + (uint32_t)(fb * 68 + fs * 16) * 4;
                #pragma unroll
                for (int j = 0; j < 4; j++) cp16(d + j * 16, fsrc + j * 4);
                cp_commit();
            }
            for (int kb = 0; kb < 8; kb++) {
                cp_wait0();
                __syncthreads();
                if (kb < 7) {
                    uint32_t d = ((kb & 1) ? hsAu : hsBu) + (uint32_t)(fb * 68 + fs * 16) * 4;
                    const float* s = fsrc + (kb + 1) * 64;
                    #pragma unroll
                    for (int j = 0; j < 4; j++) cp16(d + j * 16, s + j * 4);
                    cp_commit();
                }
                const float* hp = ((kb & 1) ? hsB : hsA) + eb * 68;
                const float* Up = &Us[kb * 256 + em];
                #pragma unroll
                for (int kk = 0; kk < 64; kk += 2) {
                    float2 hv = *reinterpret_cast<const float2*>(&hp[kk]);
                    a0 += hv.x * Up[kk * 4];
                    a1 += hv.y * Up[(kk + 1) * 4];
                }
                __syncthreads();
            }
            float acc = a0 + a1
                      + g_Z[((size_t)t * NZt + 4 * Uu + m0 + em) * Bb + eb];
            g_ze[eb][m0 + em] = acc;
            __threadfence();
            __syncthreads();
            if (tid == 0) atomicAdd(&g_eflag, 1u);
        }

        // ---- grid barrier (striped counters, monotonic targets) ----
        __syncthreads();
        if (tid == 0) { __threadfence(); atomicAdd(&g_bar4[bid & 3], 1u); }
        if (tid < 4) {
            unsigned tgt = (unsigned)(t + 1) * (unsigned)(NBLK / 4);
            while (*(volatile unsigned int*)&g_bar4[tid] < tgt) { }
            __threadfence();            // acquire: invalidate L1 before reading new h
        }
        __syncthreads();
    }
}

// ---------------- launch ----------------
extern "C" void kernel_launch(void* const* d_in, const int* in_sizes, int n_in,
                              void* d_out, int out_size) {
    (void)in_sizes; (void)n_in; (void)out_size;
    const float* x  = (const float*)d_in[0];
    const float* Wi = (const float*)d_in[1];
    const float* Ui = (const float*)d_in[2];
    const float* bi = (const float*)d_in[3];
    const float* Wf = (const float*)d_in[4];
    const float* Uf = (const float*)d_in[5];
    const float* bf = (const float*)d_in[6];
    const float* Wo = (const float*)d_in[7];
    const float* Uo = (const float*)d_in[8];
    const float* bo = (const float*)d_in[9];
    const float* Wc = (const float*)d_in[10];
    const float* Uc = (const float*)d_in[11];
    const float* bc = (const float*)d_in[12];
    const float* We = (const float*)d_in[13];
    const float* Ue = (const float*)d_in[14];
    const float* be = (const float*)d_in[15];
    float* out = (float*)d_out;

    const size_t SMEM = (size_t)SMEM_F * sizeof(float);   // 153920 B
    cudaFuncSetAttribute(recur_kernel, cudaFuncAttributeMaxDynamicSharedMemorySize, (int)SMEM);

    init_kernel<<<32, 256>>>();
    dim3 pg(33, Tt);
    precompute_kernel<<<pg, 256>>>(x, Wi, Wf, Wo, Wc, We, bi, bf, bo, bc, be);
    recur_kernel<<<NBLK, NTHR, SMEM>>>(out, Ui, Uf, Uo, Uc, Ue);
}

// round 7
// speedup vs baseline: 1.4806x; 1.0797x over previous
#include <cuda_runtime.h>
#include <math.h>
#include <stdint.h>

// Problem constants
#define Tt   512
#define Bb   64
#define Dd   256
#define Uu   512
#define Mm   64
#define NZt  2112   // 4*U + M

#define NUBLK 128   // u-blocks: 4 u-cols each (16 z-cols)
#define NEBLK 16    // e-blocks: 4 e-cols each
#define NBLK  144
#define NTHR  256

// ---------------- device scratch ----------------
__device__ float g_Z[(size_t)Tt * NZt * Bb];   // Z[t][n][b] = x_t@Wcat + bcat
__device__ float g_hT[2][Bb][Uu];              // hidden state [b][u], double buffered
__device__ float g_ze[Bb][Mm];                 // pre-softmax e logits
__device__ unsigned int g_bar4[4];             // striped grid barrier counters
__device__ unsigned int g_eflag;               // e logits ready counter

// SMEM float offsets
#define OFF_US   0              // u: [8][64k][16c] ; e: [512k][4c]
#define OFF_CR   8192           // cring [64 slot][4 u][64 b] = 16384
#define OFF_HS0  24576          // h chunk buf0 [64 b][68] = 4352
#define OFF_HS1  28928          // h chunk buf1
#define OFF_ZT   33280          // zt [16 c][65] = 1040
#define OFF_ZES  34320          // zes [64 b][65] = 4160
#define OFF_HST  38480          // h staging [4 uul][64 b] = 256
#define SMEM_F   38736          // 154944 bytes

// ---------------- PTX helpers ----------------
__device__ __forceinline__ void cp16(uint32_t dst, const float* src) {
    asm volatile("cp.async.cg.shared.global [%0], [%1], 16;" :: "r"(dst), "l"(src));
}
__device__ __forceinline__ void cp_commit() {
    asm volatile("cp.async.commit_group;");
}
__device__ __forceinline__ void cp_wait0() {
    asm volatile("cp.async.wait_group 0;");
}
__device__ __forceinline__ unsigned ld_acq(const unsigned int* p) {
    unsigned v;
    asm volatile("ld.acquire.gpu.global.u32 %0, [%1];" : "=r"(v) : "l"(p));
    return v;
}
__device__ __forceinline__ void red_rel(unsigned int* p) {
    asm volatile("red.release.gpu.global.add.u32 [%0], 1;" :: "l"(p));
}
// packed fp32x2 FMA (FFMA2) — bit-identical to 2x IEEE fp32 FMA
__device__ __forceinline__ unsigned long long pack2(float a, float b) {
    unsigned long long r;
    asm("mov.b64 %0, {%1, %2};" : "=l"(r) : "f"(a), "f"(b));
    return r;
}
__device__ __forceinline__ void fma2(unsigned long long& d,
                                     unsigned long long a, unsigned long long b) {
    asm("fma.rn.f32x2 %0, %1, %2, %0;" : "+l"(d) : "l"(a), "l"(b));
}
__device__ __forceinline__ void unpack2(unsigned long long v, float& a, float& b) {
    asm("mov.b64 {%0, %1}, %2;" : "=f"(a), "=f"(b) : "l"(v));
}

// ---------------- init ----------------
__global__ void init_kernel() {
    int tid = blockIdx.x * blockDim.x + threadIdx.x;
    float* h0 = &g_hT[0][0][0];
    for (int i = tid; i < 2 * Bb * Uu; i += gridDim.x * blockDim.x) h0[i] = 0.0f;
    if (tid < 4) g_bar4[tid] = 0u;
    if (tid == 4) g_eflag = 0u;
}

// ---------------- precompute: Z[t][n][b] = bcat[n] + sum_k x[b][t][k]*Wcat[k][n] ----------------
__global__ __launch_bounds__(256) void precompute_kernel(
    const float* __restrict__ x,
    const float* __restrict__ Wi, const float* __restrict__ Wf,
    const float* __restrict__ Wo, const float* __restrict__ Wc,
    const float* __restrict__ We,
    const float* __restrict__ bi, const float* __restrict__ bf,
    const float* __restrict__ bo, const float* __restrict__ bc,
    const float* __restrict__ be)
{
    __shared__ float xs[64 * 65];
    __shared__ float Ws[64 * 64];

    const int nt  = blockIdx.x;     // 0..32  (0..31: gates, 32: e)
    const int t   = blockIdx.y;
    const int tid = threadIdx.x;

    const float* W; const float* bv;
    switch (nt >> 3) {
        case 0:  W = Wi; bv = bi; break;
        case 1:  W = Wf; bv = bf; break;
        case 2:  W = Wo; bv = bo; break;
        case 3:  W = Wc; bv = bc; break;
        default: W = We; bv = be; break;
    }
    const int stride = (nt < 32) ? Uu : Mm;
    const int col0   = (nt & 7) * 64;

    const int tx = tid & 15, ty = tid >> 4;

    unsigned long long acc01[4], acc23[4];
    {
        float b0 = bv[col0 + tx * 4 + 0];
        float b1 = bv[col0 + tx * 4 + 1];
        float b2 = bv[col0 + tx * 4 + 2];
        float b3 = bv[col0 + tx * 4 + 3];
        unsigned long long p01 = pack2(b0, b1), p23 = pack2(b2, b3);
        #pragma unroll
        for (int i = 0; i < 4; i++) { acc01[i] = p01; acc23[i] = p23; }
    }

    for (int kb = 0; kb < 4; kb++) {
        __syncthreads();
        #pragma unroll
        for (int l = 0; l < 16; l++) {
            int idx = l * 256 + tid;
            int b = idx >> 6, kk = idx & 63;
            xs[b * 65 + kk] = x[(size_t)b * Tt * Dd + (size_t)t * Dd + kb * 64 + kk];
        }
        #pragma unroll
        for (int l = 0; l < 16; l++) {
            int idx = l * 256 + tid;
            int kk = idx >> 6, nn = idx & 63;
            Ws[kk * 64 + nn] = W[(size_t)(kb * 64 + kk) * stride + col0 + nn];
        }
        __syncthreads();
        #pragma unroll 16
        for (int kk = 0; kk < 64; kk++) {
            ulonglong2 wv = *reinterpret_cast<const ulonglong2*>(&Ws[kk * 64 + tx * 4]);
            #pragma unroll
            for (int i = 0; i < 4; i++) {
                float xv = xs[(ty * 4 + i) * 65 + kk];
                unsigned long long xx = pack2(xv, xv);
                fma2(acc01[i], xx, wv.x);
                fma2(acc23[i], xx, wv.y);
            }
        }
    }

    float a[4][4];
    #pragma unroll
    for (int i = 0; i < 4; i++) {
        unpack2(acc01[i], a[i][0], a[i][1]);
        unpack2(acc23[i], a[i][2], a[i][3]);
    }
    #pragma unroll
    for (int j = 0; j < 4; j++) {
        int n = nt * 64 + tx * 4 + j;
        float4 v = make_float4(a[0][j], a[1][j], a[2][j], a[3][j]);
        *reinterpret_cast<float4*>(&g_Z[((size_t)t * NZt + n) * Bb + ty * 4]) = v;
    }
}

// ---------------- persistent recurrent kernel ----------------
__global__ __launch_bounds__(NTHR, 1) void recur_kernel(
    float* __restrict__ out,
    const float* __restrict__ Ui, const float* __restrict__ Uf,
    const float* __restrict__ Uo, const float* __restrict__ Uc,
    const float* __restrict__ Ue)
{
    extern __shared__ float sm[];
    float* Us  = sm + OFF_US;
    float* cr  = sm + OFF_CR;
    float* hsA = sm + OFF_HS0;
    float* hsB = sm + OFF_HS1;
    float* zt  = sm + OFF_ZT;
    float* zes = sm + OFF_ZES;
    float* hst = sm + OFF_HST;

    const uint32_t smem_u = (uint32_t)__cvta_generic_to_shared(sm);
    const uint32_t hsAu = smem_u + OFF_HS0 * 4;
    const uint32_t hsBu = smem_u + OFF_HS1 * 4;

    const int bid = blockIdx.x;
    const int tid = threadIdx.x;
    const bool isE = (bid >= NUBLK);

    // --- load persistent U slice (once) ---
    if (!isE) {
        const int u0 = bid * 4;
        const int tc = tid & 15;                 // column c = gate*4 + uul
        const float* Ug;
        switch (tc >> 2) {
            case 0:  Ug = Ui; break;
            case 1:  Ug = Uf; break;
            case 2:  Ug = Uo; break;
            default: Ug = Uc; break;
        }
        const int lc = u0 + (tc & 3);
        for (int k = tid >> 4; k < Uu; k += NTHR / 16)
            Us[k * 16 + tc] = Ug[(size_t)k * Uu + lc];
    } else {
        const int m0 = (bid - NUBLK) * 4;
        const int tc = tid & 3;
        for (int k = tid >> 2; k < Uu; k += NTHR / 4)
            Us[k * 4 + tc] = Ue[(size_t)k * Mm + m0 + tc];
    }
    __syncthreads();

    // GEMM maps
    const int tx = tid & 3, ty = tid >> 2;        // u-blocks: col group / batch row
    const int fb = tid >> 2, fs = tid & 3;        // fill map: row b, 64B segment

    for (int t = 0; t < Tt; t++) {
        const float* hsrc = &g_hT[t & 1][0][0];   // [64 b][512 u]
        const float* fsrc = hsrc + (size_t)fb * Uu + fs * 16;

        if (!isE) {
            const int u0 = bid * 4;

            // Z loads for epilogue (independent, hidden behind GEMM)
            float zl0, zl1, zl2, zl3;
            {
                const float* zp = &g_Z[((size_t)t * NZt + tx * Uu + u0) * Bb + ty];
                zl0 = __ldcs(zp);
                zl1 = __ldcs(zp + 64);
                zl2 = __ldcs(zp + 128);
                zl3 = __ldcs(zp + 192);
            }

            // prologue: fill chunk 0 (async, L2-direct)
            {
                uint32_t d = hsAu + (uint32_t)(fb * 68 + fs * 16) * 4;
                #pragma unroll
                for (int j = 0; j < 4; j++) cp16(d + j * 16, fsrc + j * 4);
                cp_commit();
            }

            unsigned long long acc01 = 0ull, acc23 = 0ull;

            // ---- GEMM: z = h @ U_slice, cp.async double-buffered, FFMA2 ----
            for (int kb = 0; kb < 8; kb++) {
                cp_wait0();
                __syncthreads();
                if (kb < 7) {
                    uint32_t d = ((kb & 1) ? hsAu : hsBu) + (uint32_t)(fb * 68 + fs * 16) * 4;
                    const float* s = fsrc + (kb + 1) * 64;
                    #pragma unroll
                    for (int j = 0; j < 4; j++) cp16(d + j * 16, s + j * 4);
                    cp_commit();
                }
                const float* hp = ((kb & 1) ? hsB : hsA) + ty * 68;
                const float* Ub = &Us[kb * 1024 + tx * 4];
                #pragma unroll
                for (int kk = 0; kk < 64; kk += 2) {
                    float2 hv = *reinterpret_cast<const float2*>(&hp[kk]);
                    ulonglong2 ua = *reinterpret_cast<const ulonglong2*>(&Ub[kk * 16]);
                    ulonglong2 ub = *reinterpret_cast<const ulonglong2*>(&Ub[kk * 16 + 16]);
                    unsigned long long h0 = pack2(hv.x, hv.x);
                    unsigned long long h1 = pack2(hv.y, hv.y);
                    fma2(acc01, h0, ua.x);
                    fma2(acc23, h0, ua.y);
                    fma2(acc01, h1, ub.x);
                    fma2(acc23, h1, ub.y);
                }
                __syncthreads();
            }
            // epilogue: add Z, stash in zt[c][b]
            {
                float a0, a1, a2, a3;
                unpack2(acc01, a0, a1);
                unpack2(acc23, a2, a3);
                zt[(tx * 4 + 0) * 65 + ty] = a0 + zl0;
                zt[(tx * 4 + 1) * 65 + ty] = a1 + zl1;
                zt[(tx * 4 + 2) * 65 + ty] = a2 + zl2;
                zt[(tx * 4 + 3) * 65 + ty] = a3 + zl3;
            }

            // ---- wait for e logits (acquire poll, no fence) ----
            if (tid == 0) {
                unsigned tgt = (unsigned)(t + 1) * (unsigned)NEBLK;
                while (ld_acq(&g_eflag) < tgt) { }
            }
            __syncthreads();

            // ---- softmax: direct from L2 (__ldcg), 4 lanes per batch row ----
            {
                const int sb = tid >> 2, sq = tid & 3;
                const float4* zrow = reinterpret_cast<const float4*>(&g_ze[sb][sq * 16]);
                float4 v0 = __ldcg(zrow);
                float4 v1 = __ldcg(zrow + 1);
                float4 v2 = __ldcg(zrow + 2);
                float4 v3 = __ldcg(zrow + 3);
                float v[16] = {v0.x, v0.y, v0.z, v0.w, v1.x, v1.y, v1.z, v1.w,
                               v2.x, v2.y, v2.z, v2.w, v3.x, v3.y, v3.z, v3.w};
                float mx = -1e30f;
                #pragma unroll
                for (int i = 0; i < 16; i++) mx = fmaxf(mx, v[i]);
                mx = fmaxf(mx, __shfl_xor_sync(0xffffffffu, mx, 1));
                mx = fmaxf(mx, __shfl_xor_sync(0xffffffffu, mx, 2));
                float s = 0.f;
                #pragma unroll
                for (int i = 0; i < 16; i++) { v[i] = __expf(v[i] - mx); s += v[i]; }
                s += __shfl_xor_sync(0xffffffffu, s, 1);
                s += __shfl_xor_sync(0xffffffffu, s, 2);
                float inv = 1.0f / s;
                #pragma unroll
                for (int i = 0; i < 16; i++) zes[sb * 65 + sq * 16 + i] = v[i] * inv;
            }
            __syncthreads();

            // ---- phase 2: memory read + update (uul = tid>>6, b = tid&63) ----
            {
                const int uul = tid >> 6, b = tid & 63;
                const int mlim = (t < 64) ? t : 64;
                float p0 = 0.f, p1 = 0.f, p2 = 0.f, p3 = 0.f;
                const float* zr = &zes[b * 65];
                int m = 0;
                for (; m + 4 <= mlim; m += 4) {
                    int s0 = (t - 1 - m) & 63, s1 = (t - 2 - m) & 63;
                    int s2 = (t - 3 - m) & 63, s3 = (t - 4 - m) & 63;
                    p0 += zr[m]     * cr[(s0 * 4 + uul) * 64 + b];
                    p1 += zr[m + 1] * cr[(s1 * 4 + uul) * 64 + b];
                    p2 += zr[m + 2] * cr[(s2 * 4 + uul) * 64 + b];
                    p3 += zr[m + 3] * cr[(s3 * 4 + uul) * 64 + b];
                }
                for (; m < mlim; m++)
                    p0 += zr[m] * cr[(((t - 1 - m) & 63) * 4 + uul) * 64 + b];
                float mc = (p0 + p1) + (p2 + p3);

                float iv = zt[(uul)      * 65 + b];
                float fv = zt[(4 + uul)  * 65 + b];
                float ov = zt[(8 + uul)  * 65 + b];
                float cv = zt[(12 + uul) * 65 + b];
                iv = 1.0f / (1.0f + __expf(-iv));
                fv = 1.0f / (1.0f + __expf(-fv));
                ov = 1.0f / (1.0f + __expf(-ov));
                cv = tanhf(cv);
                float c = fv * mc + iv * cv;
                float h = ov * tanhf(c);
                cr[((t & 63) * 4 + uul) * 64 + b] = c;             // block-private ring
                hst[uul * 64 + b] = h;                             // stage for vector store
            }
            __syncthreads();
            // vectorized h + out stores (STG.128)
            if (tid < 64) {
                const int b = tid;
                float4 hv = make_float4(hst[b], hst[64 + b], hst[128 + b], hst[192 + b]);
                *reinterpret_cast<float4*>(&g_hT[(t + 1) & 1][b][u0]) = hv;
                *reinterpret_cast<float4*>(&out[((size_t)b * Tt + t) * Uu + u0]) = hv;
            }
        } else {
            // ---- e-block: small GEMM producing ze ----
            const int m0 = (bid - NUBLK) * 4;
            const int eb = tid >> 2, em = tid & 3;
            float a0 = 0.f, a1 = 0.f;

            {
                uint32_t d = hsAu + (uint32_t)(fb * 68 + fs * 16) * 4;
                #pragma unroll
                for (int j = 0; j < 4; j++) cp16(d + j * 16, fsrc + j * 4);
                cp_commit();
            }
            for (int kb = 0; kb < 8; kb++) {
                cp_wait0();
                __syncthreads();
                if (kb < 7) {
                    uint32_t d = ((kb & 1) ? hsAu : hsBu) + (uint32_t)(fb * 68 + fs * 16) * 4;
                    const float* s = fsrc + (kb + 1) * 64;
                    #pragma unroll
                    for (int j = 0; j < 4; j++) cp16(d + j * 16, s + j * 4);
                    cp_commit();
                }
                const float* hp = ((kb & 1) ? hsB : hsA) + eb * 68;
                const float* Up = &Us[kb * 256 + em];
                #pragma unroll
                for (int kk = 0; kk < 64; kk += 2) {
                    float2 hv = *reinterpret_cast<const float2*>(&hp[kk]);
                    a0 += hv.x * Up[kk * 4];
                    a1 += hv.y * Up[(kk + 1) * 4];
                }
                __syncthreads();
            }
            float acc = a0 + a1
                      + __ldcs(&g_Z[((size_t)t * NZt + 4 * Uu + m0 + em) * Bb + eb]);
            g_ze[eb][m0 + em] = acc;
            __syncthreads();
            if (tid == 0) red_rel(&g_eflag);       // release: orders ze stores
        }

        // ---- grid barrier (release arrivals, acquire polls) ----
        __syncthreads();
        if (tid == 0) red_rel(&g_bar4[bid & 3]);
        if (tid < 4) {
            unsigned tgt = (unsigned)(t + 1) * (unsigned)(NBLK / 4);
            while (ld_acq(&g_bar4[tid]) < tgt) { }
        }
        __syncthreads();
    }
}

// ---------------- launch ----------------
extern "C" void kernel_launch(void* const* d_in, const int* in_sizes, int n_in,
                              void* d_out, int out_size) {
    (void)in_sizes; (void)n_in; (void)out_size;
    const float* x  = (const float*)d_in[0];
    const float* Wi = (const float*)d_in[1];
    const float* Ui = (const float*)d_in[2];
    const float* bi = (const float*)d_in[3];
    const float* Wf = (const float*)d_in[4];
    const float* Uf = (const float*)d_in[5];
    const float* bf = (const float*)d_in[6];
    const float* Wo = (const float*)d_in[7];
    const float* Uo = (const float*)d_in[8];
    const float* bo = (const float*)d_in[9];
    const float* Wc = (const float*)d_in[10];
    const float* Uc = (const float*)d_in[11];
    const float* bc = (const float*)d_in[12];
    const float* We = (const float*)d_in[13];
    const float* Ue = (const float*)d_in[14];
    const float* be = (const float*)d_in[15];
    float* out = (float*)d_out;

    const size_t SMEM = (size_t)SMEM_F * sizeof(float);   // 154944 B
    cudaFuncSetAttribute(recur_kernel, cudaFuncAttributeMaxDynamicSharedMemorySize, (int)SMEM);

    init_kernel<<<32, 256>>>();
    dim3 pg(33, Tt);
    precompute_kernel<<<pg, 256>>>(x, Wi, Wf, Wo, Wc, We, bi, bf, bo, bc, be);
    recur_kernel<<<NBLK, NTHR, SMEM>>>(out, Ui, Uf, Uo, Uc, Ue);
}

// round 8
// speedup vs baseline: 1.5054x; 1.0167x over previous
#include <cuda_runtime.h>
#include <math.h>
#include <stdint.h>

// Problem constants
#define Tt   512
#define Bb   64
#define Dd   256
#define Uu   512
#define Mm   64
#define NZt  2112   // 4*U + M

#define NUBLK 128   // u-blocks: 4 u-cols each (16 z-cols)
#define NEBLK 16    // e-blocks: 4 e-cols each
#define NBLK  144
#define NTHR  512

// ---------------- device scratch ----------------
__device__ float g_Z[(size_t)Tt * NZt * Bb];   // Z[t][n][b] = x_t@Wcat + bcat
__device__ float g_hT[2][Bb][Uu];              // hidden state [b][u], double buffered
__device__ float g_ze[Bb][Mm];                 // pre-softmax e logits
__device__ unsigned int g_hdone[4];            // striped h-ready counters (32 u-blocks each)
__device__ unsigned int g_eflag;               // e logits ready counter

// SMEM float offsets
#define OFF_US   0              // u: [8x64k][16c] ; e: [512k][4c]
#define OFF_CR   8192           // cring [64 slot][4 u][64 b] = 16384
#define OFF_H    24576          // 4 h buffers x [64 b][68] = 4*4352
#define OFF_ZT   41984          // zt [16 c][65] = 1040
#define OFF_PS   43024          // partial-sum buffer [16][65] / [256] = 1040
#define OFF_ZES  44064          // softmax probs [64 b][65] = 4160
#define OFF_HST  48224          // h staging [4 uul][64 b] = 256
#define SMEM_F   48480          // 193920 bytes

// ---------------- PTX helpers ----------------
__device__ __forceinline__ void cp16(uint32_t dst, const float* src) {
    asm volatile("cp.async.cg.shared.global [%0], [%1], 16;" :: "r"(dst), "l"(src));
}
__device__ __forceinline__ void cp_commit() {
    asm volatile("cp.async.commit_group;");
}
__device__ __forceinline__ void cp_wait0() {
    asm volatile("cp.async.wait_group 0;");
}
__device__ __forceinline__ unsigned ld_acq(const unsigned int* p) {
    unsigned v;
    asm volatile("ld.acquire.gpu.global.u32 %0, [%1];" : "=r"(v) : "l"(p));
    return v;
}
__device__ __forceinline__ void red_rel(unsigned int* p) {
    asm volatile("red.release.gpu.global.add.u32 [%0], 1;" :: "l"(p));
}
// packed fp32x2 FMA (FFMA2) — bit-identical to 2x IEEE fp32 FMA
__device__ __forceinline__ unsigned long long pack2(float a, float b) {
    unsigned long long r;
    asm("mov.b64 %0, {%1, %2};" : "=l"(r) : "f"(a), "f"(b));
    return r;
}
__device__ __forceinline__ void fma2(unsigned long long& d,
                                     unsigned long long a, unsigned long long b) {
    asm("fma.rn.f32x2 %0, %1, %2, %0;" : "+l"(d) : "l"(a), "l"(b));
}
__device__ __forceinline__ void unpack2(unsigned long long v, float& a, float& b) {
    asm("mov.b64 {%0, %1}, %2;" : "=f"(a), "=f"(b) : "l"(v));
}

// ---------------- init ----------------
__global__ void init_kernel() {
    int tid = blockIdx.x * blockDim.x + threadIdx.x;
    float* h0 = &g_hT[0][0][0];
    for (int i = tid; i < 2 * Bb * Uu; i += gridDim.x * blockDim.x) h0[i] = 0.0f;
    if (tid < 4) g_hdone[tid] = 0u;
    if (tid == 4) g_eflag = 0u;
}

// ---------------- precompute: Z[t][n][b] = bcat[n] + sum_k x[b][t][k]*Wcat[k][n] ----------------
__global__ __launch_bounds__(256) void precompute_kernel(
    const float* __restrict__ x,
    const float* __restrict__ Wi, const float* __restrict__ Wf,
    const float* __restrict__ Wo, const float* __restrict__ Wc,
    const float* __restrict__ We,
    const float* __restrict__ bi, const float* __restrict__ bf,
    const float* __restrict__ bo, const float* __restrict__ bc,
    const float* __restrict__ be)
{
    __shared__ float xs[64 * 65];
    __shared__ float Ws[64 * 64];

    const int nt  = blockIdx.x;     // 0..32  (0..31: gates, 32: e)
    const int t   = blockIdx.y;
    const int tid = threadIdx.x;

    const float* W; const float* bv;
    switch (nt >> 3) {
        case 0:  W = Wi; bv = bi; break;
        case 1:  W = Wf; bv = bf; break;
        case 2:  W = Wo; bv = bo; break;
        case 3:  W = Wc; bv = bc; break;
        default: W = We; bv = be; break;
    }
    const int stride = (nt < 32) ? Uu : Mm;
    const int col0   = (nt & 7) * 64;

    const int tx = tid & 15, ty = tid >> 4;

    unsigned long long acc01[4], acc23[4];
    {
        float b0 = bv[col0 + tx * 4 + 0];
        float b1 = bv[col0 + tx * 4 + 1];
        float b2 = bv[col0 + tx * 4 + 2];
        float b3 = bv[col0 + tx * 4 + 3];
        unsigned long long p01 = pack2(b0, b1), p23 = pack2(b2, b3);
        #pragma unroll
        for (int i = 0; i < 4; i++) { acc01[i] = p01; acc23[i] = p23; }
    }

    for (int kb = 0; kb < 4; kb++) {
        __syncthreads();
        #pragma unroll
        for (int l = 0; l < 16; l++) {
            int idx = l * 256 + tid;
            int b = idx >> 6, kk = idx & 63;
            xs[b * 65 + kk] = x[(size_t)b * Tt * Dd + (size_t)t * Dd + kb * 64 + kk];
        }
        #pragma unroll
        for (int l = 0; l < 16; l++) {
            int idx = l * 256 + tid;
            int kk = idx >> 6, nn = idx & 63;
            Ws[kk * 64 + nn] = W[(size_t)(kb * 64 + kk) * stride + col0 + nn];
        }
        __syncthreads();
        #pragma unroll 16
        for (int kk = 0; kk < 64; kk++) {
            ulonglong2 wv = *reinterpret_cast<const ulonglong2*>(&Ws[kk * 64 + tx * 4]);
            #pragma unroll
            for (int i = 0; i < 4; i++) {
                float xv = xs[(ty * 4 + i) * 65 + kk];
                unsigned long long xx = pack2(xv, xv);
                fma2(acc01[i], xx, wv.x);
                fma2(acc23[i], xx, wv.y);
            }
        }
    }

    float a[4][4];
    #pragma unroll
    for (int i = 0; i < 4; i++) {
        unpack2(acc01[i], a[i][0], a[i][1]);
        unpack2(acc23[i], a[i][2], a[i][3]);
    }
    #pragma unroll
    for (int j = 0; j < 4; j++) {
        int n = nt * 64 + tx * 4 + j;
        float4 v = make_float4(a[0][j], a[1][j], a[2][j], a[3][j]);
        *reinterpret_cast<float4*>(&g_Z[((size_t)t * NZt + n) * Bb + ty * 4]) = v;
    }
}

// ---------------- persistent recurrent kernel ----------------
// 144 blocks x 512 threads, split-K over two 256-k halves.
// No end-of-step barrier: producer-side h-ready counters only.
__global__ __launch_bounds__(NTHR, 1) void recur_kernel(
    float* __restrict__ out,
    const float* __restrict__ Ui, const float* __restrict__ Uf,
    const float* __restrict__ Uo, const float* __restrict__ Uc,
    const float* __restrict__ Ue)
{
    extern __shared__ float sm[];
    float* Us  = sm + OFF_US;
    float* cr  = sm + OFF_CR;
    float* zt  = sm + OFF_ZT;
    float* ps  = sm + OFF_PS;
    float* zes = sm + OFF_ZES;
    float* hst = sm + OFF_HST;

    const uint32_t smem_u = (uint32_t)__cvta_generic_to_shared(sm);

    const int bid = blockIdx.x;
    const int tid = threadIdx.x;
    const bool isE = (bid >= NUBLK);

    // --- load persistent U slice (once) ---
    if (!isE) {
        const int u0 = bid * 4;
        const int tc = tid & 15;                 // column c = gate*4 + uul
        const float* Ug;
        switch (tc >> 2) {
            case 0:  Ug = Ui; break;
            case 1:  Ug = Uf; break;
            case 2:  Ug = Uo; break;
            default: Ug = Uc; break;
        }
        const int lc = u0 + (tc & 3);
        for (int k = tid >> 4; k < Uu; k += NTHR / 16)
            Us[k * 16 + tc] = Ug[(size_t)k * Uu + lc];
    } else {
        const int m0 = (bid - NUBLK) * 4;
        const int tc = tid & 3;
        for (int k = tid >> 2; k < Uu; k += NTHR / 4)
            Us[k * 4 + tc] = Ue[(size_t)k * Mm + m0 + tc];
    }
    __syncthreads();

    // thread maps
    const int half = tid >> 8;                    // K half: [half*256, half*256+256)
    const int tx   = tid & 3;                     // col group (u) / e col (e)
    const int ty   = (tid >> 2) & 63;             // batch row
    // fill map: row ty, 64B segment tx, within this thread's K half
    const uint32_t fd[2] = {
        smem_u + (uint32_t)(OFF_H + (half * 2 + 0) * 4352 + ty * 68 + tx * 16) * 4,
        smem_u + (uint32_t)(OFF_H + (half * 2 + 1) * 4352 + ty * 68 + tx * 16) * 4
    };
    float* const hbuf[2] = { sm + OFF_H + (half * 2 + 0) * 4352,
                             sm + OFF_H + (half * 2 + 1) * 4352 };

    for (int t = 0; t < Tt; t++) {
        const float* hsrc = &g_hT[t & 1][0][0];   // [64 b][512 u]
        const float* fsrc = hsrc + (size_t)ty * Uu + half * 256 + tx * 16;

        if (!isE) {
            const int u0 = bid * 4;

            // Z loads (independent of h) — issue BEFORE the gate
            float zl0 = 0.f, zl1 = 0.f, zl2 = 0.f, zl3 = 0.f;
            if (half == 0) {
                const float* zp = &g_Z[((size_t)t * NZt + tx * Uu + u0) * Bb + ty];
                zl0 = __ldcs(zp);
                zl1 = __ldcs(zp + 64);
                zl2 = __ldcs(zp + 128);
                zl3 = __ldcs(zp + 192);
            }

            // ---- step-start gate: h[t] ready (producer counters) ----
            if (tid < 4) {
                unsigned tgt = (unsigned)t * 32u;
                while (ld_acq(&g_hdone[tid]) < tgt) { }
            }
            __syncthreads();

            // prologue: fill round-0 chunk (async, L2-direct)
            {
                #pragma unroll
                for (int j = 0; j < 4; j++) cp16(fd[0] + j * 16, fsrc + j * 4);
                cp_commit();
            }

            unsigned long long acc01 = 0ull, acc23 = 0ull;

            // ---- GEMM: z = h @ U_slice, 4 rounds of 64 k (per half) ----
            for (int r = 0; r < 4; r++) {
                cp_wait0();
                __syncthreads();
                if (r < 3) {
                    uint32_t d = fd[(r + 1) & 1];
                    const float* s = fsrc + (r + 1) * 64;
                    #pragma unroll
                    for (int j = 0; j < 4; j++) cp16(d + j * 16, s + j * 4);
                    cp_commit();
                }
                const float* hp = hbuf[r & 1] + ty * 68;
                const float* Ub = &Us[(half * 256 + r * 64) * 16 + tx * 4];
                #pragma unroll
                for (int kk = 0; kk < 64; kk += 2) {
                    float2 hv = *reinterpret_cast<const float2*>(&hp[kk]);
                    ulonglong2 ua = *reinterpret_cast<const ulonglong2*>(&Ub[kk * 16]);
                    ulonglong2 ub = *reinterpret_cast<const ulonglong2*>(&Ub[kk * 16 + 16]);
                    unsigned long long h0 = pack2(hv.x, hv.x);
                    unsigned long long h1 = pack2(hv.y, hv.y);
                    fma2(acc01, h0, ua.x);
                    fma2(acc23, h0, ua.y);
                    fma2(acc01, h1, ub.x);
                    fma2(acc23, h1, ub.y);
                }
                __syncthreads();
            }

            // epilogue: half1 stashes partials; tid0 polls e-flag concurrently
            {
                float a0, a1, a2, a3;
                unpack2(acc01, a0, a1);
                unpack2(acc23, a2, a3);
                if (half == 1) {
                    ps[(tx * 4 + 0) * 65 + ty] = a0;
                    ps[(tx * 4 + 1) * 65 + ty] = a1;
                    ps[(tx * 4 + 2) * 65 + ty] = a2;
                    ps[(tx * 4 + 3) * 65 + ty] = a3;
                }
                if (tid == 0) {
                    unsigned tgt = (unsigned)(t + 1) * (unsigned)NEBLK;
                    while (ld_acq(&g_eflag) < tgt) { }
                }
                __syncthreads();
                if (half == 0) {
                    zt[(tx * 4 + 0) * 65 + ty] = a0 + ps[(tx * 4 + 0) * 65 + ty] + zl0;
                    zt[(tx * 4 + 1) * 65 + ty] = a1 + ps[(tx * 4 + 1) * 65 + ty] + zl1;
                    zt[(tx * 4 + 2) * 65 + ty] = a2 + ps[(tx * 4 + 2) * 65 + ty] + zl2;
                    zt[(tx * 4 + 3) * 65 + ty] = a3 + ps[(tx * 4 + 3) * 65 + ty] + zl3;
                }
            }

            // ---- softmax: 8 lanes per batch row, direct from L2 ----
            {
                const int sb = tid >> 3, sq = tid & 7;
                const float4* zrow = reinterpret_cast<const float4*>(&g_ze[sb][sq * 8]);
                float4 v0 = __ldcg(zrow);
                float4 v1 = __ldcg(zrow + 1);
                float v[8] = {v0.x, v0.y, v0.z, v0.w, v1.x, v1.y, v1.z, v1.w};
                float mx = -1e30f;
                #pragma unroll
                for (int i = 0; i < 8; i++) mx = fmaxf(mx, v[i]);
                mx = fmaxf(mx, __shfl_xor_sync(0xffffffffu, mx, 1));
                mx = fmaxf(mx, __shfl_xor_sync(0xffffffffu, mx, 2));
                mx = fmaxf(mx, __shfl_xor_sync(0xffffffffu, mx, 4));
                float s = 0.f;
                #pragma unroll
                for (int i = 0; i < 8; i++) { v[i] = __expf(v[i] - mx); s += v[i]; }
                s += __shfl_xor_sync(0xffffffffu, s, 1);
                s += __shfl_xor_sync(0xffffffffu, s, 2);
                s += __shfl_xor_sync(0xffffffffu, s, 4);
                float inv = 1.0f / s;
                #pragma unroll
                for (int i = 0; i < 8; i++) zes[sb * 65 + sq * 8 + i] = v[i] * inv;
            }
            __syncthreads();

            // ---- phase 2: memory read, m-loop split across halves ----
            {
                const int item = tid & 255;
                const int uul = item >> 6, b = item & 63;
                const int mlim = (t < 64) ? t : 64;
                const int lo = half * 32;
                const int hi = (mlim < lo + 32) ? mlim : lo + 32;
                float p = 0.f;
                const float* zr = &zes[b * 65];
                #pragma unroll 4
                for (int m = lo; m < hi; m++)
                    p += zr[m] * cr[(((t - 1 - m) & 63) * 4 + uul) * 64 + b];
                if (half == 1) ps[item] = p;
                __syncthreads();
                if (half == 0) {
                    float mc = p + ps[item];
                    float iv = zt[(uul)      * 65 + b];
                    float fv = zt[(4 + uul)  * 65 + b];
                    float ov = zt[(8 + uul)  * 65 + b];
                    float cv = zt[(12 + uul) * 65 + b];
                    iv = 1.0f / (1.0f + __expf(-iv));
                    fv = 1.0f / (1.0f + __expf(-fv));
                    ov = 1.0f / (1.0f + __expf(-ov));
                    cv = tanhf(cv);
                    float c = fv * mc + iv * cv;
                    float h = ov * tanhf(c);
                    cr[((t & 63) * 4 + uul) * 64 + b] = c;         // block-private ring
                    hst[uul * 64 + b] = h;
                }
            }
            __syncthreads();
            // vectorized h + out stores (STG.128), then release arrival
            if (tid < 64) {
                const int b = tid;
                float4 hv = make_float4(hst[b], hst[64 + b], hst[128 + b], hst[192 + b]);
                *reinterpret_cast<float4*>(&g_hT[(t + 1) & 1][b][u0]) = hv;
                *reinterpret_cast<float4*>(&out[((size_t)b * Tt + t) * Uu + u0]) = hv;
            }
            __syncthreads();
            if (tid == 0) red_rel(&g_hdone[bid & 3]);
        } else {
            // ---- e-block: small GEMM producing ze (split-K) ----
            const int m0 = (bid - NUBLK) * 4;
            float zl = 0.f;
            if (half == 0)
                zl = __ldcs(&g_Z[((size_t)t * NZt + 4 * Uu + m0 + tx) * Bb + ty]);

            // gate (backoff poll — e-blocks have slack)
            if (tid < 4) {
                unsigned tgt = (unsigned)t * 32u;
                while (ld_acq(&g_hdone[tid]) < tgt) __nanosleep(128);
            }
            __syncthreads();

            {
                #pragma unroll
                for (int j = 0; j < 4; j++) cp16(fd[0] + j * 16, fsrc + j * 4);
                cp_commit();
            }
            float a0 = 0.f, a1 = 0.f;
            for (int r = 0; r < 4; r++) {
                cp_wait0();
                __syncthreads();
                if (r < 3) {
                    uint32_t d = fd[(r + 1) & 1];
                    const float* s = fsrc + (r + 1) * 64;
                    #pragma unroll
                    for (int j = 0; j < 4; j++) cp16(d + j * 16, s + j * 4);
                    cp_commit();
                }
                const float* hp = hbuf[r & 1] + ty * 68;
                const float* Up = &Us[(half * 256 + r * 64) * 4 + tx];
                #pragma unroll
                for (int kk = 0; kk < 64; kk += 2) {
                    float2 hv = *reinterpret_cast<const float2*>(&hp[kk]);
                    a0 += hv.x * Up[kk * 4];
                    a1 += hv.y * Up[(kk + 1) * 4];
                }
                __syncthreads();
            }
            float a = a0 + a1;
            if (half == 1) ps[tid & 255] = a;
            __syncthreads();
            if (half == 0)
                g_ze[ty][m0 + tx] = a + ps[tid & 255] + zl;
            __syncthreads();
            if (tid == 0) red_rel(&g_eflag);       // release: orders ze stores
        }
    }
}

// ---------------- launch ----------------
extern "C" void kernel_launch(void* const* d_in, const int* in_sizes, int n_in,
                              void* d_out, int out_size) {
    (void)in_sizes; (void)n_in; (void)out_size;
    const float* x  = (const float*)d_in[0];
    const float* Wi = (const float*)d_in[1];
    const float* Ui = (const float*)d_in[2];
    const float* bi = (const float*)d_in[3];
    const float* Wf = (const float*)d_in[4];
    const float* Uf = (const float*)d_in[5];
    const float* bf = (const float*)d_in[6];
    const float* Wo = (const float*)d_in[7];
    const float* Uo = (const float*)d_in[8];
    const float* bo = (const float*)d_in[9];
    const float* Wc = (const float*)d_in[10];
    const float* Uc = (const float*)d_in[11];
    const float* bc = (const float*)d_in[12];
    const float* We = (const float*)d_in[13];
    const float* Ue = (const float*)d_in[14];
    const float* be = (const float*)d_in[15];
    float* out = (float*)d_out;

    const size_t SMEM = (size_t)SMEM_F * sizeof(float);   // 193920 B
    cudaFuncSetAttribute(recur_kernel, cudaFuncAttributeMaxDynamicSharedMemorySize, (int)SMEM);

    init_kernel<<<32, 256>>>();
    dim3 pg(33, Tt);
    precompute_kernel<<<pg, 256>>>(x, Wi, Wf, Wo, Wc, We, bi, bf, bo, bc, be);
    recur_kernel<<<NBLK, NTHR, SMEM>>>(out, Ui, Uf, Uo, Uc, Ue);
}